// round 10
// baseline (speedup 1.0000x reference)
#include <cuda_runtime.h>
#include <cuda_bf16.h>
#include <cstdint>
#include <math.h>

#define NN 6144
#define NFEAT 512
#define NHID 256
#define NCLASS 8
#define ADIM 128

// ---------------- scratch (device globals; no allocation allowed) ----------
__device__ float g_adj[(size_t)NN * NN];   // combined adjacency
__device__ float g_S[(size_t)NN * NN];     // masked scores P -> consumed by Xt
__device__ float g_nz[NN * 3];
__device__ float g_Wc[NN * 16];            // fused Wa@Wagg, padded 16/row
__device__ float g_bc[3];
__device__ float2 g_stats[NN];             // per-row (max, 1/sum) of P
__device__ float g_XW1[NN * NHID];
__device__ float g_XW1T[NHID * NN];
__device__ float g_x[NN * NHID];
__device__ float g_Q[NN * NHID];
__device__ float g_Kh[NN * NHID];
__device__ float g_V[NN * NHID];
__device__ float g_VT[NHID * NN];
__device__ float g_Xt[NN * NHID];
__device__ float g_XW2[NN * NCLASS];
__device__ float g_W1T[NHID * NFEAT];
__device__ float g_WqT[NHID * NHID];
__device__ float g_WkT[NHID * NHID];
__device__ float g_WvT[NHID * NHID];

// ================= helpers ==================================================
__device__ __forceinline__ uint32_t smem_to_u32(const void* p) {
    uint32_t a;
    asm("{ .reg .u64 t; cvta.to.shared.u64 t, %1; cvt.u32.u64 %0, t; }" : "=r"(a) : "l"(p));
    return a;
}

// split fp32 x4 -> bf16 hi pair + lo pair (lo = exact residual, re-rounded)
__device__ __forceinline__ void split4(float4 v, uint2& hi, uint2& lo) {
    uint32_t h0, h1, l0, l1;
    asm("cvt.rn.bf16x2.f32 %0, %1, %2;" : "=r"(h0) : "f"(v.y), "f"(v.x));
    asm("cvt.rn.bf16x2.f32 %0, %1, %2;" : "=r"(h1) : "f"(v.w), "f"(v.z));
    float r0 = v.x - __uint_as_float(h0 << 16);
    float r1 = v.y - __uint_as_float(h0 & 0xffff0000u);
    float r2 = v.z - __uint_as_float(h1 << 16);
    float r3 = v.w - __uint_as_float(h1 & 0xffff0000u);
    asm("cvt.rn.bf16x2.f32 %0, %1, %2;" : "=r"(l0) : "f"(r1), "f"(r0));
    asm("cvt.rn.bf16x2.f32 %0, %1, %2;" : "=r"(l1) : "f"(r3), "f"(r2));
    hi.x = h0; hi.y = h1; lo.x = l0; lo.y = l1;
}

#define LDSM4(R, ADDR) \
    asm volatile("ldmatrix.sync.aligned.m8n8.x4.shared.b16 {%0,%1,%2,%3}, [%4];" \
                 : "=r"((R)[0]), "=r"((R)[1]), "=r"((R)[2]), "=r"((R)[3]) : "r"(ADDR))

#define MMA16816(D, A, B) \
    asm volatile("mma.sync.aligned.m16n8k16.row.col.f32.bf16.bf16.f32 " \
                 "{%0,%1,%2,%3}, {%4,%5,%6,%7}, {%8,%9}, {%0,%1,%2,%3};" \
                 : "+f"((D)[0]), "+f"((D)[1]), "+f"((D)[2]), "+f"((D)[3]) \
                 : "r"((A)[0]), "r"((A)[1]), "r"((A)[2]), "r"((A)[3]), \
                   "r"((B)[0]), "r"((B)[1]))

// ================== bf16x3 mma.sync GEMM: C[M,N] = A[M,K] @ B[N,K]^T ========
// fp32 in/out, split on the fly. BMx128 tile, BK=32, double-buffered smem.
// EPI bit0 = +bias[col], bit1 = relu, bit2 = multiply by g_adj tile (mask).
// EXPA: transform A values v -> exp(v - M[row]) * inv[row]  (softmax on load)
#define RS 40                                  // smem row stride (bf16)
#define ARR_BQ ((uint32_t)(128 * RS * 2))      // B array bytes (10240)
#define SMEM_OF(BM) (2 * (2u * (uint32_t)(BM) * RS * 2u + 2u * ARR_BQ))

template<int EPI, int BM, int EXPA>
__global__ __launch_bounds__(256, (BM == 64) ? 2 : 1)
void mma_gemm_kernel(const float* A0, const float* A1, const float* A2,
                     const float* B0, const float* B1, const float* B2,
                     const float* bi0, const float* bi1, const float* bi2,
                     float* C0, float* C1, float* C2,
                     int ldc, int K)
{
    constexpr int MT = BM / 32;                      // 16-row frags per warp
    constexpr int ITA = BM / 32;                     // A float4 loads / thread
    constexpr uint32_t ARR_A = (uint32_t)BM * RS * 2;
    constexpr uint32_t STGB = 2 * ARR_A + 2 * ARR_BQ;

    extern __shared__ uint8_t sm8[];
    const uint32_t sbase = smem_to_u32(sm8);

    const int z = blockIdx.z;
    const float* A = (z == 0 ? A0 : (z == 1 ? A1 : A2)) + (size_t)blockIdx.x * BM * K;
    const float* B = (z == 0 ? B0 : (z == 1 ? B1 : B2)) + (size_t)blockIdx.y * 128 * K;
    const float* bias = (z == 0 ? bi0 : (z == 1 ? bi1 : bi2));
    float* C = (z == 0 ? C0 : (z == 1 ? C1 : C2))
               + (size_t)blockIdx.x * BM * ldc + (size_t)blockIdx.y * 128;

    const int tid = threadIdx.x, lane = tid & 31, wid = tid >> 5;
    const int wm = wid & 1;        // 2 M-slabs of BM/2
    const int wn = wid >> 1;       // 4 N-slabs of 32

    float acc[MT][4][4];
#pragma unroll
    for (int a = 0; a < MT; a++)
#pragma unroll
        for (int b = 0; b < 4; b++)
#pragma unroll
            for (int c = 0; c < 4; c++) acc[a][b][c] = 0.f;

    const int nchunk = K >> 5;
    float4 ld[ITA + 4];

    // ---- prologue: load chunk 0 ----
#pragma unroll
    for (int i = 0; i < ITA + 4; i++) {
        const bool isA = (i < ITA);
        int e = isA ? (tid + i * 256) : (tid + (i - ITA) * 256);
        int r = e >> 3, c = e & 7;
        const float* src = isA ? A : B;
        ld[i] = *reinterpret_cast<const float4*>(src + (size_t)r * K + c * 4);
    }
    // ---- convert chunk 0 into stage 0 ----
#pragma unroll
    for (int i = 0; i < ITA + 4; i++) {
        const bool isA = (i < ITA);
        int e = isA ? (tid + i * 256) : (tid + (i - ITA) * 256);
        int r = e >> 3, c = e & 7;
        float4 v = ld[i];
        if (EXPA && isA) {
            float2 st = g_stats[blockIdx.x * BM + r];
            v.x = __expf(v.x - st.x) * st.y; v.y = __expf(v.y - st.x) * st.y;
            v.z = __expf(v.z - st.x) * st.y; v.w = __expf(v.w - st.x) * st.y;
        }
        uint2 hi, lo; split4(v, hi, lo);
        uint32_t off = (isA ? 0u : 2u * ARR_A) + (uint32_t)(r * RS + c * 4) * 2u;
        *reinterpret_cast<uint2*>(sm8 + off) = hi;
        *reinterpret_cast<uint2*>(sm8 + off + (isA ? ARR_A : ARR_BQ)) = lo;
    }
    __syncthreads();

    for (int kc = 0; kc < nchunk; kc++) {
        const int s = kc & 1;
        // ---- issue next chunk's global loads (latency hidden by MMAs) ----
        if (kc + 1 < nchunk) {
            const int k0n = (kc + 1) << 5;
#pragma unroll
            for (int i = 0; i < ITA + 4; i++) {
                const bool isA = (i < ITA);
                int e = isA ? (tid + i * 256) : (tid + (i - ITA) * 256);
                int r = e >> 3, c = e & 7;
                const float* src = isA ? A : B;
                ld[i] = *reinterpret_cast<const float4*>(src + (size_t)r * K + k0n + c * 4);
            }
        }
        // ---- MMA on stage s ----
        const uint32_t st = sbase + (uint32_t)s * STGB;
#pragma unroll
        for (int ks = 0; ks < 2; ks++) {
            const int k0 = ks * 16;
            uint32_t ah[MT][4], al[MT][4], bh[4][2], bl[4][2];
            const uint32_t a_addr = st +
                (uint32_t)(((wm * (BM / 2) + (lane & 15)) * RS + k0 + ((lane >> 4) << 3)) * 2);
#pragma unroll
            for (int mt = 0; mt < MT; mt++) {
                LDSM4(ah[mt], a_addr + (uint32_t)(mt * 16 * RS * 2));
                LDSM4(al[mt], a_addr + ARR_A + (uint32_t)(mt * 16 * RS * 2));
            }
            const uint32_t b_addr = st + 2u * ARR_A +
                (uint32_t)(((wn * 32 + (lane & 7) + ((lane >> 4) << 3)) * RS
                            + k0 + (((lane >> 3) & 1) << 3)) * 2);
            {
                uint32_t t[4];
                LDSM4(t, b_addr);
                bh[0][0] = t[0]; bh[0][1] = t[1]; bh[1][0] = t[2]; bh[1][1] = t[3];
                LDSM4(t, b_addr + (uint32_t)(16 * RS * 2));
                bh[2][0] = t[0]; bh[2][1] = t[1]; bh[3][0] = t[2]; bh[3][1] = t[3];
                LDSM4(t, b_addr + ARR_BQ);
                bl[0][0] = t[0]; bl[0][1] = t[1]; bl[1][0] = t[2]; bl[1][1] = t[3];
                LDSM4(t, b_addr + ARR_BQ + (uint32_t)(16 * RS * 2));
                bl[2][0] = t[0]; bl[2][1] = t[1]; bl[3][0] = t[2]; bl[3][1] = t[3];
            }
#pragma unroll
            for (int mt = 0; mt < MT; mt++)
#pragma unroll
                for (int nt = 0; nt < 4; nt++) {
                    MMA16816(acc[mt][nt], ah[mt], bh[nt]);   // hi*hi
                    MMA16816(acc[mt][nt], ah[mt], bl[nt]);   // hi*lo
                    MMA16816(acc[mt][nt], al[mt], bh[nt]);   // lo*hi
                }
        }
        // ---- convert next chunk into the other stage ----
        if (kc + 1 < nchunk) {
            __syncthreads();
            const uint32_t so = (uint32_t)(s ^ 1) * STGB;
#pragma unroll
            for (int i = 0; i < ITA + 4; i++) {
                const bool isA = (i < ITA);
                int e = isA ? (tid + i * 256) : (tid + (i - ITA) * 256);
                int r = e >> 3, c = e & 7;
                float4 v = ld[i];
                if (EXPA && isA) {
                    float2 stv = g_stats[blockIdx.x * BM + r];
                    v.x = __expf(v.x - stv.x) * stv.y; v.y = __expf(v.y - stv.x) * stv.y;
                    v.z = __expf(v.z - stv.x) * stv.y; v.w = __expf(v.w - stv.x) * stv.y;
                }
                uint2 hi, lo; split4(v, hi, lo);
                uint32_t off = so + (isA ? 0u : 2u * ARR_A)
                             + (uint32_t)(r * RS + c * 4) * 2u;
                *reinterpret_cast<uint2*>(sm8 + off) = hi;
                *reinterpret_cast<uint2*>(sm8 + off + (isA ? ARR_A : ARR_BQ)) = lo;
            }
            __syncthreads();
        }
    }

    // ---- epilogue ----
#pragma unroll
    for (int mt = 0; mt < MT; mt++) {
        int row0 = wm * (BM / 2) + mt * 16 + (lane >> 2);
#pragma unroll
        for (int nt = 0; nt < 4; nt++) {
            int col = wn * 32 + nt * 8 + (lane & 3) * 2;
            float b0 = 0.f, b1 = 0.f;
            if (EPI & 1) { b0 = bias[blockIdx.y * 128 + col]; b1 = bias[blockIdx.y * 128 + col + 1]; }
            float2 v0, v1;
            v0.x = acc[mt][nt][0] + b0; v0.y = acc[mt][nt][1] + b1;
            v1.x = acc[mt][nt][2] + b0; v1.y = acc[mt][nt][3] + b1;
            if (EPI & 4) {   // adjacency mask multiply (S-GEMM)
                const float* ap = g_adj + (size_t)(blockIdx.x * BM + row0) * NN
                                + blockIdx.y * 128 + col;
                v0.x *= ap[0]; v0.y *= ap[1];
                v1.x *= ap[(size_t)8 * NN]; v1.y *= ap[(size_t)8 * NN + 1];
            }
            if (EPI & 2) {
                v0.x = fmaxf(v0.x, 0.f); v0.y = fmaxf(v0.y, 0.f);
                v1.x = fmaxf(v1.x, 0.f); v1.y = fmaxf(v1.y, 0.f);
            }
            *reinterpret_cast<float2*>(C + (size_t)row0 * ldc + col) = v0;
            *reinterpret_cast<float2*>(C + (size_t)(row0 + 8) * ldc + col) = v1;
        }
    }
}

// ================== transpose fp32 [R,C] -> [C,R] ===========================
__global__ __launch_bounds__(256)
void transpose_kernel(const float* __restrict__ src, float* __restrict__ dst, int R, int C)
{
    __shared__ float t[32][33];
    int c0 = blockIdx.x * 32, r0 = blockIdx.y * 32;
    int x = threadIdx.x, y = threadIdx.y;  // 32 x 8
#pragma unroll
    for (int j = 0; j < 32; j += 8)
        t[y + j][x] = src[(size_t)(r0 + y + j) * C + c0 + x];
    __syncthreads();
#pragma unroll
    for (int j = 0; j < 32; j += 8)
        dst[(size_t)(c0 + y + j) * R + r0 + x] = t[x][y + j];
}

// ---------------- Wc = Wa_i @ Wagg_block_i  (+ combined bias) ---------------
__global__ __launch_bounds__(256)
void wc_kernel(const float* __restrict__ Wa1, const float* __restrict__ Wa2,
               const float* __restrict__ Wa3, const float* __restrict__ Wagg,
               const float* __restrict__ ba1, const float* __restrict__ ba2,
               const float* __restrict__ ba3, const float* __restrict__ bagg)
{
    int idx = blockIdx.x * 256 + threadIdx.x;   // 3*NN threads
    if (idx < 3 * NN) {
        int i = idx / NN, c = idx % NN;
        const float* Wa = (i == 0) ? Wa1 : ((i == 1) ? Wa2 : Wa3);
        float a0 = 0.f, a1 = 0.f, a2 = 0.f;
#pragma unroll 4
        for (int a = 0; a < ADIM; a++) {
            float w = Wa[(size_t)c * ADIM + a];
            const float* wg = Wagg + (size_t)(i * ADIM + a) * 3;
            a0 = fmaf(w, wg[0], a0); a1 = fmaf(w, wg[1], a1); a2 = fmaf(w, wg[2], a2);
        }
        g_Wc[(size_t)c * 16 + i * 4 + 0] = a0;
        g_Wc[(size_t)c * 16 + i * 4 + 1] = a1;
        g_Wc[(size_t)c * 16 + i * 4 + 2] = a2;
        g_Wc[(size_t)c * 16 + i * 4 + 3] = 0.f;
    }
    if (blockIdx.x == 0 && threadIdx.x < 3) {
        int j = threadIdx.x;
        float b = bagg[j];
        for (int a = 0; a < ADIM; a++) {
            b = fmaf(ba1[a], Wagg[(size_t)a * 3 + j], b);
            b = fmaf(ba2[a], Wagg[(size_t)(ADIM + a) * 3 + j], b);
            b = fmaf(ba3[a], Wagg[(size_t)(2 * ADIM + a) * 3 + j], b);
        }
        g_bc[j] = b;
    }
}

// ---------------- z4 = Σ_i adj_i @ Wc_i + bc ; 3-way softmax -> nz ----------
// 4 rows per block; replaces the 87-GF z-GEMM with one 453MB read.
__global__ __launch_bounds__(256)
void z4nz_kernel(const float* __restrict__ a0, const float* __restrict__ a1,
                 const float* __restrict__ a2, float* __restrict__ out_nz)
{
    __shared__ float red[8][12];
    int r0 = blockIdx.x * 4;
    int tid = threadIdx.x, warp = tid >> 5, lane = tid & 31;
    float acc[4][3];
#pragma unroll
    for (int rr = 0; rr < 4; rr++)
#pragma unroll
        for (int j = 0; j < 3; j++) acc[rr][j] = 0.f;

    for (int it = 0; it < NN / 4 / 256; it++) {
        int idx = tid + it * 256;            // float4 index along columns
        const float4* wcp = reinterpret_cast<const float4*>(g_Wc + (size_t)idx * 64);
        float4 wc[16];
#pragma unroll
        for (int q = 0; q < 16; q++) wc[q] = wcp[q];
#pragma unroll
        for (int rr = 0; rr < 4; rr++) {
            float4 v0 = reinterpret_cast<const float4*>(a0 + (size_t)(r0 + rr) * NN)[idx];
            float4 v1 = reinterpret_cast<const float4*>(a1 + (size_t)(r0 + rr) * NN)[idx];
            float4 v2 = reinterpret_cast<const float4*>(a2 + (size_t)(r0 + rr) * NN)[idx];
            const float av[3][4] = {{v0.x, v0.y, v0.z, v0.w},
                                    {v1.x, v1.y, v1.z, v1.w},
                                    {v2.x, v2.y, v2.z, v2.w}};
#pragma unroll
            for (int cc = 0; cc < 4; cc++)
#pragma unroll
                for (int i = 0; i < 3; i++) {
                    float4 w = wc[cc * 4 + i];
                    float a = av[i][cc];
                    acc[rr][0] = fmaf(a, w.x, acc[rr][0]);
                    acc[rr][1] = fmaf(a, w.y, acc[rr][1]);
                    acc[rr][2] = fmaf(a, w.z, acc[rr][2]);
                }
        }
    }
#pragma unroll
    for (int rr = 0; rr < 4; rr++)
#pragma unroll
        for (int j = 0; j < 3; j++) {
            float v = acc[rr][j];
#pragma unroll
            for (int off = 16; off; off >>= 1) v += __shfl_xor_sync(0xffffffffu, v, off);
            if (lane == 0) red[warp][rr * 3 + j] = v;
        }
    __syncthreads();
    if (tid == 0) {
#pragma unroll
        for (int rr = 0; rr < 4; rr++) {
            float z0 = g_bc[0], z1 = g_bc[1], z2 = g_bc[2];
#pragma unroll
            for (int w = 0; w < 8; w++) {
                z0 += red[w][rr * 3 + 0]; z1 += red[w][rr * 3 + 1]; z2 += red[w][rr * 3 + 2];
            }
            float m = fmaxf(z0, fmaxf(z1, z2));
            float e0 = __expf(z0 - m), e1 = __expf(z1 - m), e2 = __expf(z2 - m);
            float inv = 1.f / (e0 + e1 + e2);
            int row = r0 + rr;
            g_nz[row * 3 + 0] = e0 * inv; g_nz[row * 3 + 1] = e1 * inv; g_nz[row * 3 + 2] = e2 * inv;
            if (out_nz) {
                out_nz[row * 3 + 0] = e0 * inv; out_nz[row * 3 + 1] = e1 * inv;
                out_nz[row * 3 + 2] = e2 * inv;
            }
        }
    }
}

// ---------------- adj[r,c] = sum_i nz[c,i] * adj_i[r,c] ---------------------
__global__ __launch_bounds__(256)
void combine_adj_kernel(const float* __restrict__ a0,
                        const float* __restrict__ a1,
                        const float* __restrict__ a2)
{
    size_t idx = (size_t)blockIdx.x * 256 + threadIdx.x;   // float4 index
    int c = (int)(idx % (NN / 4)) * 4;
    float4 v0 = ((const float4*)a0)[idx];
    float4 v1 = ((const float4*)a1)[idx];
    float4 v2 = ((const float4*)a2)[idx];
    float4 r;
    r.x = g_nz[(c + 0) * 3] * v0.x + g_nz[(c + 0) * 3 + 1] * v1.x + g_nz[(c + 0) * 3 + 2] * v2.x;
    r.y = g_nz[(c + 1) * 3] * v0.y + g_nz[(c + 1) * 3 + 1] * v1.y + g_nz[(c + 1) * 3 + 2] * v2.y;
    r.z = g_nz[(c + 2) * 3] * v0.z + g_nz[(c + 2) * 3 + 1] * v1.z + g_nz[(c + 2) * 3 + 2] * v2.z;
    r.w = g_nz[(c + 3) * 3] * v0.w + g_nz[(c + 3) * 3 + 1] * v1.w + g_nz[(c + 3) * 3 + 2] * v2.w;
    ((float4*)g_adj)[idx] = r;
}

// ---------------- per-row online (max, 1/sum_exp) of P ----------------------
__global__ __launch_bounds__(256)
void stats_kernel()
{
    __shared__ float2 sred[8];
    int row = blockIdx.x, tid = threadIdx.x, warp = tid >> 5, lane = tid & 31;
    const float* pr = g_S + (size_t)row * NN;
    float m = -3.4e38f, s = 0.f;
    for (int j = tid; j < NN; j += 256) {
        float v = pr[j];
        if (v > m) { s = s * __expf(m - v) + 1.f; m = v; }
        else       { s += __expf(v - m); }
    }
#pragma unroll
    for (int off = 16; off; off >>= 1) {
        float m2 = __shfl_xor_sync(0xffffffffu, m, off);
        float s2 = __shfl_xor_sync(0xffffffffu, s, off);
        float M = fmaxf(m, m2);
        s = s * __expf(m - M) + s2 * __expf(m2 - M);
        m = M;
    }
    if (lane == 0) sred[warp] = make_float2(m, s);
    __syncthreads();
    if (tid == 0) {
        float M = sred[0].x, S = sred[0].y;
#pragma unroll
        for (int w = 1; w < 8; w++) {
            float m2 = sred[w].x, s2 = sred[w].y;
            float Mn = fmaxf(M, m2);
            S = S * __expf(M - Mn) + s2 * __expf(m2 - Mn);
            M = Mn;
        }
        g_stats[row] = make_float2(M, 1.f / S);
    }
}

// ---------------- XW2 = X_tilde @ W2  (N=8) ---------------------------------
__global__ __launch_bounds__(256)
void xw2_kernel(const float* __restrict__ W2)
{
    __shared__ float sW[NHID][9];
    int tid = threadIdx.x;
    for (int i = tid; i < NHID * NCLASS; i += 256) sW[i / 8][i % 8] = W2[i];
    __syncthreads();
    int warp = tid >> 5, lane = tid & 31;
    int row = blockIdx.x * 8 + warp;
    const float* xr = g_Xt + (size_t)row * NHID;
    float acc[8] = {0, 0, 0, 0, 0, 0, 0, 0};
#pragma unroll
    for (int it = 0; it < NHID / 32; it++) {
        int k = it * 32 + lane;
        float xv = xr[k];
#pragma unroll
        for (int j = 0; j < 8; j++) acc[j] = fmaf(xv, sW[k][j], acc[j]);
    }
#pragma unroll
    for (int j = 0; j < 8; j++)
#pragma unroll
        for (int off = 16; off; off >>= 1)
            acc[j] += __shfl_xor_sync(0xffffffffu, acc[j], off);
    if (lane == 0) {
#pragma unroll
        for (int j = 0; j < 8; j++) g_XW2[(size_t)row * 8 + j] = acc[j];
    }
}

// ---------------- z = adj @ XW2 + b2 ; softmax rows -> out ------------------
__global__ __launch_bounds__(256)
void z_out_kernel(const float* __restrict__ b2, float* __restrict__ out)
{
    __shared__ float sW[512][9];
    int tid = threadIdx.x, warp = tid >> 5, lane = tid & 31;
    int row = blockIdx.x * 8 + warp;
    const float* ar = g_adj + (size_t)row * NN;
    float acc[8] = {0, 0, 0, 0, 0, 0, 0, 0};
    for (int c0 = 0; c0 < NN; c0 += 512) {
        __syncthreads();
        for (int i = tid; i < 512 * 8; i += 256) sW[i / 8][i % 8] = g_XW2[(size_t)(c0) * 8 + i];
        __syncthreads();
#pragma unroll
        for (int it = 0; it < 16; it++) {
            int k = it * 32 + lane;
            float a = ar[c0 + k];
#pragma unroll
            for (int j = 0; j < 8; j++) acc[j] = fmaf(a, sW[k][j], acc[j]);
        }
    }
#pragma unroll
    for (int j = 0; j < 8; j++)
#pragma unroll
        for (int off = 16; off; off >>= 1)
            acc[j] += __shfl_xor_sync(0xffffffffu, acc[j], off);
    if (lane == 0) {
        float z[8]; float m = -3.4e38f;
#pragma unroll
        for (int j = 0; j < 8; j++) { z[j] = acc[j] + b2[j]; m = fmaxf(m, z[j]); }
        float s = 0.f;
#pragma unroll
        for (int j = 0; j < 8; j++) { z[j] = __expf(z[j] - m); s += z[j]; }
        float inv = 1.f / s;
#pragma unroll
        for (int j = 0; j < 8; j++) out[(size_t)row * 8 + j] = z[j] * inv;
    }
}

// ---------------- launch ----------------------------------------------------
extern "C" void kernel_launch(void* const* d_in, const int* in_sizes, int n_in,
                              void* d_out, int out_size)
{
    const float* adj0 = (const float*)d_in[0];
    const float* adj1 = (const float*)d_in[1];
    const float* adj2 = (const float*)d_in[2];
    const float* feat = (const float*)d_in[3];
    const float* Wa1  = (const float*)d_in[4];
    const float* ba1  = (const float*)d_in[5];
    const float* Wa2  = (const float*)d_in[6];
    const float* ba2  = (const float*)d_in[7];
    const float* Wa3  = (const float*)d_in[8];
    const float* ba3  = (const float*)d_in[9];
    const float* Wagg = (const float*)d_in[10];
    const float* bagg = (const float*)d_in[11];
    const float* W1   = (const float*)d_in[12];
    const float* b1   = (const float*)d_in[13];
    const float* Wq   = (const float*)d_in[14];
    const float* bq   = (const float*)d_in[15];
    const float* Wk   = (const float*)d_in[16];
    const float* bk   = (const float*)d_in[17];
    const float* Wv   = (const float*)d_in[18];
    const float* bv   = (const float*)d_in[19];
    const float* W2   = (const float*)d_in[20];
    const float* b2   = (const float*)d_in[21];
    float* out = (float*)d_out;

    float *adjC, *S, *XW1, *XW1T, *x, *Q, *Kh, *V, *VT, *Xt;
    float *W1T, *WqT, *WkT, *WvT;
    cudaGetSymbolAddress((void**)&adjC, g_adj);
    cudaGetSymbolAddress((void**)&S,    g_S);
    cudaGetSymbolAddress((void**)&XW1,  g_XW1);
    cudaGetSymbolAddress((void**)&XW1T, g_XW1T);
    cudaGetSymbolAddress((void**)&x,    g_x);
    cudaGetSymbolAddress((void**)&Q,    g_Q);
    cudaGetSymbolAddress((void**)&Kh,   g_Kh);
    cudaGetSymbolAddress((void**)&V,    g_V);
    cudaGetSymbolAddress((void**)&VT,   g_VT);
    cudaGetSymbolAddress((void**)&Xt,   g_Xt);
    cudaGetSymbolAddress((void**)&W1T,  g_W1T);
    cudaGetSymbolAddress((void**)&WqT,  g_WqT);
    cudaGetSymbolAddress((void**)&WkT,  g_WkT);
    cudaGetSymbolAddress((void**)&WvT,  g_WvT);

    cudaFuncSetAttribute(mma_gemm_kernel<0,64,0>, cudaFuncAttributeMaxDynamicSharedMemorySize, (int)SMEM_OF(64));
    cudaFuncSetAttribute(mma_gemm_kernel<1,64,0>, cudaFuncAttributeMaxDynamicSharedMemorySize, (int)SMEM_OF(64));
    cudaFuncSetAttribute(mma_gemm_kernel<3,64,0>, cudaFuncAttributeMaxDynamicSharedMemorySize, (int)SMEM_OF(64));
    cudaFuncSetAttribute(mma_gemm_kernel<2,64,1>, cudaFuncAttributeMaxDynamicSharedMemorySize, (int)SMEM_OF(64));
    cudaFuncSetAttribute(mma_gemm_kernel<4,128,0>, cudaFuncAttributeMaxDynamicSharedMemorySize, (int)SMEM_OF(128));

    dim3 tb(32, 8);
    // small weight transposes ([K,N] -> [N,K] for the MMA B operand)
    transpose_kernel<<<dim3(NHID / 32, NFEAT / 32), tb>>>(W1, W1T, NFEAT, NHID);
    transpose_kernel<<<dim3(NHID / 32, NHID / 32), tb>>>(Wq, WqT, NHID, NHID);
    transpose_kernel<<<dim3(NHID / 32, NHID / 32), tb>>>(Wk, WkT, NHID, NHID);
    transpose_kernel<<<dim3(NHID / 32, NHID / 32), tb>>>(Wv, WvT, NHID, NHID);

    // 1) Wc = Wa_i @ Wagg_block_i  (tiny; replaces the 87-GF z-GEMM)
    wc_kernel<<<(3 * NN + 255) / 256, 256>>>(Wa1, Wa2, Wa3, Wagg, ba1, ba2, ba3, bagg);

    // 2) z4 = Σ adj_i @ Wc_i + bc ; nz = softmax3 (bandwidth pass)
    float* out_nz = (out_size >= NN * (NCLASS + 3)) ? out + (size_t)NN * NCLASS : nullptr;
    z4nz_kernel<<<NN / 4, 256>>>(adj0, adj1, adj2, out_nz);

    // 3) adj = column-weighted combination
    combine_adj_kernel<<<(NN / 4) * (NN / 256), 256>>>(adj0, adj1, adj2);

    // 4) XW1 = features @ W1
    mma_gemm_kernel<0,64,0><<<dim3(NN / 64, NHID / 128, 1), 256, SMEM_OF(64)>>>(
        feat, feat, feat, W1T, W1T, W1T, nullptr, nullptr, nullptr,
        XW1, XW1, XW1, NHID, NFEAT);
    transpose_kernel<<<dim3(NHID / 32, NN / 32), tb>>>(XW1, XW1T, NN, NHID);

    // 5) x = relu(adj @ XW1 + b1)
    mma_gemm_kernel<3,64,0><<<dim3(NN / 64, NHID / 128, 1), 256, SMEM_OF(64)>>>(
        adjC, adjC, adjC, XW1T, XW1T, XW1T, b1, b1, b1,
        x, x, x, NHID, NN);

    // 6) Q, K, V fused over blockIdx.z
    mma_gemm_kernel<1,64,0><<<dim3(NN / 64, NHID / 128, 3), 256, SMEM_OF(64)>>>(
        x, x, x, WqT, WkT, WvT, bq, bk, bv,
        Q, Kh, V, NHID, NHID);
    transpose_kernel<<<dim3(NHID / 32, NN / 32), tb>>>(V, VT, NN, NHID);

    // 7) P = adj * (Q @ K^T)   (mask fused into epilogue)
    mma_gemm_kernel<4,128,0><<<dim3(NN / 128, NN / 128, 1), 256, SMEM_OF(128)>>>(
        Q, Q, Q, Kh, Kh, Kh, nullptr, nullptr, nullptr,
        S, S, S, NN, NHID);

    // 8) per-row (max, 1/sum_exp) of P  (gcn_norm == identity, skipped)
    stats_kernel<<<NN, 256>>>();

    // 9) X_tilde = relu(softmax(P) @ V)  — exp applied in the A-loader
    mma_gemm_kernel<2,64,1><<<dim3(NN / 64, NHID / 128, 1), 256, SMEM_OF(64)>>>(
        S, S, S, VT, VT, VT, nullptr, nullptr, nullptr,
        Xt, Xt, Xt, NHID, NN);

    // 10) XW2 = X_tilde @ W2
    xw2_kernel<<<NN / 8, 256>>>(W2);

    // 11) z = adj @ XW2 + b2 ; row softmax -> out[0 : N*8)
    z_out_kernel<<<NN / 8, 256>>>(b2, out);
}

// round 11
// speedup vs baseline: 1.0933x; 1.0933x over previous
#include <cuda_runtime.h>
#include <cuda_bf16.h>
#include <cstdint>
#include <math.h>

#define NN 6144
#define NFEAT 512
#define NHID 256
#define NCLASS 8
#define ADIM 128

// ---------------- scratch (device globals; no allocation allowed) ----------
__device__ float g_adj[(size_t)NN * NN];   // combined adjacency
__device__ float g_S[(size_t)NN * NN];     // scores -> attention (in-place)
__device__ float g_nz[NN * 3];
__device__ float g_Wc[NN * 16];            // fused Wa@Wagg, padded 16/row
__device__ float g_bc[3];
__device__ float g_XW1[NN * NHID];
__device__ float g_XW1T[NHID * NN];
__device__ float g_x[NN * NHID];
__device__ float g_Q[NN * NHID];
__device__ float g_Kh[NN * NHID];
__device__ float g_V[NN * NHID];
__device__ float g_VT[NHID * NN];
__device__ float g_Xt[NN * NHID];
__device__ float g_XW2[NN * NCLASS];
__device__ float g_W1T[NHID * NFEAT];
__device__ float g_WqT[NHID * NHID];
__device__ float g_WkT[NHID * NHID];
__device__ float g_WvT[NHID * NHID];

// ================= helpers ==================================================
__device__ __forceinline__ uint32_t smem_to_u32(const void* p) {
    uint32_t a;
    asm("{ .reg .u64 t; cvta.to.shared.u64 t, %1; cvt.u32.u64 %0, t; }" : "=r"(a) : "l"(p));
    return a;
}

// split fp32 x4 -> bf16 hi pair + lo pair (lo = exact residual, re-rounded)
__device__ __forceinline__ void split4(float4 v, uint2& hi, uint2& lo) {
    uint32_t h0, h1, l0, l1;
    asm("cvt.rn.bf16x2.f32 %0, %1, %2;" : "=r"(h0) : "f"(v.y), "f"(v.x));
    asm("cvt.rn.bf16x2.f32 %0, %1, %2;" : "=r"(h1) : "f"(v.w), "f"(v.z));
    float r0 = v.x - __uint_as_float(h0 << 16);
    float r1 = v.y - __uint_as_float(h0 & 0xffff0000u);
    float r2 = v.z - __uint_as_float(h1 << 16);
    float r3 = v.w - __uint_as_float(h1 & 0xffff0000u);
    asm("cvt.rn.bf16x2.f32 %0, %1, %2;" : "=r"(l0) : "f"(r1), "f"(r0));
    asm("cvt.rn.bf16x2.f32 %0, %1, %2;" : "=r"(l1) : "f"(r3), "f"(r2));
    hi.x = h0; hi.y = h1; lo.x = l0; lo.y = l1;
}

#define LDSM4(R, ADDR) \
    asm volatile("ldmatrix.sync.aligned.m8n8.x4.shared.b16 {%0,%1,%2,%3}, [%4];" \
                 : "=r"((R)[0]), "=r"((R)[1]), "=r"((R)[2]), "=r"((R)[3]) : "r"(ADDR))

#define MMA16816(D, A, B) \
    asm volatile("mma.sync.aligned.m16n8k16.row.col.f32.bf16.bf16.f32 " \
                 "{%0,%1,%2,%3}, {%4,%5,%6,%7}, {%8,%9}, {%0,%1,%2,%3};" \
                 : "+f"((D)[0]), "+f"((D)[1]), "+f"((D)[2]), "+f"((D)[3]) \
                 : "r"((A)[0]), "r"((A)[1]), "r"((A)[2]), "r"((A)[3]), \
                   "r"((B)[0]), "r"((B)[1]))

// ================== bf16x3 mma.sync GEMM: C[M,N] = A[M,K] @ B[N,K]^T ========
// fp32 in/out, split on the fly. 128x128 tile, BK=32, double-buffered smem.
// EPI bit0 = +bias[col], bit1 = relu. blockIdx.z selects {A,B,bias,C}.
#define RS 40                       // smem row stride (bf16) -> conflict-free
#define ARR_B ((uint32_t)(128 * RS * 2))   // 10240 bytes per array
#define STG_B (4u * ARR_B)                 // Ah, Al, Bh, Bl per stage
#define MMA_SMEM (2 * (int)STG_B)          // 81920 bytes

template<int EPI>
__global__ __launch_bounds__(256, 1)
void mma_gemm_kernel(const float* A0, const float* A1, const float* A2,
                     const float* B0, const float* B1, const float* B2,
                     const float* bi0, const float* bi1, const float* bi2,
                     float* C0, float* C1, float* C2,
                     int ldc, int K)
{
    extern __shared__ uint8_t sm8[];
    const uint32_t sbase = smem_to_u32(sm8);

    const int z = blockIdx.z;
    const float* A = (z == 0 ? A0 : (z == 1 ? A1 : A2)) + (size_t)blockIdx.x * 128 * K;
    const float* B = (z == 0 ? B0 : (z == 1 ? B1 : B2)) + (size_t)blockIdx.y * 128 * K;
    const float* bias = (z == 0 ? bi0 : (z == 1 ? bi1 : bi2));
    float* C = (z == 0 ? C0 : (z == 1 ? C1 : C2))
               + (size_t)blockIdx.x * 128 * ldc + (size_t)blockIdx.y * 128;

    const int tid = threadIdx.x, lane = tid & 31, wid = tid >> 5;
    const int wm = wid & 1;        // 2 M-slabs of 64
    const int wn = wid >> 1;       // 4 N-slabs of 32

    float acc[4][4][4];
#pragma unroll
    for (int a = 0; a < 4; a++)
#pragma unroll
        for (int b = 0; b < 4; b++)
#pragma unroll
            for (int c = 0; c < 4; c++) acc[a][b][c] = 0.f;

    const int nchunk = K >> 5;
    float4 ld[8];

    // ---- prologue: load + convert chunk 0 ----
#pragma unroll
    for (int i = 0; i < 8; i++) {
        int e = tid + i * 256;
        int r = (e & 1023) >> 3, c = e & 7;
        const float* src = (i < 4) ? A : B;
        ld[i] = *reinterpret_cast<const float4*>(src + (size_t)r * K + c * 4);
    }
#pragma unroll
    for (int i = 0; i < 8; i++) {
        int e = tid + i * 256;
        int r = (e & 1023) >> 3, c = e & 7;
        uint2 hi, lo; split4(ld[i], hi, lo);
        uint32_t off = (i < 4 ? 0u : 2u * ARR_B) + (uint32_t)(r * RS + c * 4) * 2u;
        *reinterpret_cast<uint2*>(sm8 + off) = hi;
        *reinterpret_cast<uint2*>(sm8 + off + ARR_B) = lo;
    }
    __syncthreads();

    for (int kc = 0; kc < nchunk; kc++) {
        const int s = kc & 1;
        // ---- issue next chunk's global loads (latency hidden by MMAs) ----
        if (kc + 1 < nchunk) {
            const int k0n = (kc + 1) << 5;
#pragma unroll
            for (int i = 0; i < 8; i++) {
                int e = tid + i * 256;
                int r = (e & 1023) >> 3, c = e & 7;
                const float* src = (i < 4) ? A : B;
                ld[i] = *reinterpret_cast<const float4*>(src + (size_t)r * K + k0n + c * 4);
            }
        }
        // ---- MMA on stage s ----
        const uint32_t st = sbase + (uint32_t)s * STG_B;
#pragma unroll
        for (int ks = 0; ks < 2; ks++) {
            const int k0 = ks * 16;
            uint32_t ah[4][4], al[4][4], bh[4][2], bl[4][2];
            const uint32_t a_addr = st +
                (uint32_t)(((wm * 64 + (lane & 15)) * RS + k0 + ((lane >> 4) << 3)) * 2);
#pragma unroll
            for (int mt = 0; mt < 4; mt++) {
                LDSM4(ah[mt], a_addr + (uint32_t)(mt * 16 * RS * 2));
                LDSM4(al[mt], a_addr + ARR_B + (uint32_t)(mt * 16 * RS * 2));
            }
            const uint32_t b_addr = st + 2u * ARR_B +
                (uint32_t)(((wn * 32 + (lane & 7) + ((lane >> 4) << 3)) * RS
                            + k0 + (((lane >> 3) & 1) << 3)) * 2);
            {
                uint32_t t[4];
                LDSM4(t, b_addr);
                bh[0][0] = t[0]; bh[0][1] = t[1]; bh[1][0] = t[2]; bh[1][1] = t[3];
                LDSM4(t, b_addr + (uint32_t)(16 * RS * 2));
                bh[2][0] = t[0]; bh[2][1] = t[1]; bh[3][0] = t[2]; bh[3][1] = t[3];
                LDSM4(t, b_addr + ARR_B);
                bl[0][0] = t[0]; bl[0][1] = t[1]; bl[1][0] = t[2]; bl[1][1] = t[3];
                LDSM4(t, b_addr + ARR_B + (uint32_t)(16 * RS * 2));
                bl[2][0] = t[0]; bl[2][1] = t[1]; bl[3][0] = t[2]; bl[3][1] = t[3];
            }
#pragma unroll
            for (int mt = 0; mt < 4; mt++)
#pragma unroll
                for (int nt = 0; nt < 4; nt++) {
                    MMA16816(acc[mt][nt], ah[mt], bh[nt]);   // hi*hi
                    MMA16816(acc[mt][nt], ah[mt], bl[nt]);   // hi*lo
                    MMA16816(acc[mt][nt], al[mt], bh[nt]);   // lo*hi
                }
        }
        // ---- convert next chunk into the other stage ----
        if (kc + 1 < nchunk) {
            __syncthreads();
            const uint32_t so = (uint32_t)(s ^ 1) * STG_B;
#pragma unroll
            for (int i = 0; i < 8; i++) {
                int e = tid + i * 256;
                int r = (e & 1023) >> 3, c = e & 7;
                uint2 hi, lo; split4(ld[i], hi, lo);
                uint32_t off = so + (i < 4 ? 0u : 2u * ARR_B)
                             + (uint32_t)(r * RS + c * 4) * 2u;
                *reinterpret_cast<uint2*>(sm8 + off) = hi;
                *reinterpret_cast<uint2*>(sm8 + off + ARR_B) = lo;
            }
            __syncthreads();
        }
    }

    // ---- epilogue: c-frag -> gmem (float2 stores), bias/relu ----
#pragma unroll
    for (int mt = 0; mt < 4; mt++) {
        int row0 = wm * 64 + mt * 16 + (lane >> 2);
#pragma unroll
        for (int nt = 0; nt < 4; nt++) {
            int col = wn * 32 + nt * 8 + (lane & 3) * 2;
            float b0 = 0.f, b1 = 0.f;
            if (EPI & 1) { b0 = bias[blockIdx.y * 128 + col]; b1 = bias[blockIdx.y * 128 + col + 1]; }
            float2 v0, v1;
            v0.x = acc[mt][nt][0] + b0; v0.y = acc[mt][nt][1] + b1;
            v1.x = acc[mt][nt][2] + b0; v1.y = acc[mt][nt][3] + b1;
            if (EPI & 2) {
                v0.x = fmaxf(v0.x, 0.f); v0.y = fmaxf(v0.y, 0.f);
                v1.x = fmaxf(v1.x, 0.f); v1.y = fmaxf(v1.y, 0.f);
            }
            *reinterpret_cast<float2*>(C + (size_t)row0 * ldc + col) = v0;
            *reinterpret_cast<float2*>(C + (size_t)(row0 + 8) * ldc + col) = v1;
        }
    }
}

// ================== transpose fp32 [R,C] -> [C,R] ===========================
__global__ __launch_bounds__(256)
void transpose_kernel(const float* __restrict__ src, float* __restrict__ dst, int R, int C)
{
    __shared__ float t[32][33];
    int c0 = blockIdx.x * 32, r0 = blockIdx.y * 32;
    int x = threadIdx.x, y = threadIdx.y;  // 32 x 8
#pragma unroll
    for (int j = 0; j < 32; j += 8)
        t[y + j][x] = src[(size_t)(r0 + y + j) * C + c0 + x];
    __syncthreads();
#pragma unroll
    for (int j = 0; j < 32; j += 8)
        dst[(size_t)(c0 + y + j) * R + r0 + x] = t[x][y + j];
}

// ---------------- Wc = Wa_i @ Wagg_block_i  (+ combined bias) ---------------
__global__ __launch_bounds__(256)
void wc_kernel(const float* __restrict__ Wa1, const float* __restrict__ Wa2,
               const float* __restrict__ Wa3, const float* __restrict__ Wagg,
               const float* __restrict__ ba1, const float* __restrict__ ba2,
               const float* __restrict__ ba3, const float* __restrict__ bagg)
{
    int idx = blockIdx.x * 256 + threadIdx.x;   // 3*NN threads
    if (idx < 3 * NN) {
        int i = idx / NN, c = idx % NN;
        const float* Wa = (i == 0) ? Wa1 : ((i == 1) ? Wa2 : Wa3);
        float a0 = 0.f, a1 = 0.f, a2 = 0.f;
#pragma unroll 4
        for (int a = 0; a < ADIM; a++) {
            float w = Wa[(size_t)c * ADIM + a];
            const float* wg = Wagg + (size_t)(i * ADIM + a) * 3;
            a0 = fmaf(w, wg[0], a0); a1 = fmaf(w, wg[1], a1); a2 = fmaf(w, wg[2], a2);
        }
        g_Wc[(size_t)c * 16 + i * 4 + 0] = a0;
        g_Wc[(size_t)c * 16 + i * 4 + 1] = a1;
        g_Wc[(size_t)c * 16 + i * 4 + 2] = a2;
        g_Wc[(size_t)c * 16 + i * 4 + 3] = 0.f;
    }
    if (blockIdx.x == 0 && threadIdx.x < 3) {
        int j = threadIdx.x;
        float b = bagg[j];
        for (int a = 0; a < ADIM; a++) {
            b = fmaf(ba1[a], Wagg[(size_t)a * 3 + j], b);
            b = fmaf(ba2[a], Wagg[(size_t)(ADIM + a) * 3 + j], b);
            b = fmaf(ba3[a], Wagg[(size_t)(2 * ADIM + a) * 3 + j], b);
        }
        g_bc[j] = b;
    }
}

// ---------------- z4 = Σ_i adj_i @ Wc_i + bc ; 3-way softmax -> nz ----------
// 4 rows per block; replaces the 87-GF z-GEMM with one 453MB read.
__global__ __launch_bounds__(256)
void z4nz_kernel(const float* __restrict__ a0, const float* __restrict__ a1,
                 const float* __restrict__ a2, float* __restrict__ out_nz)
{
    __shared__ float red[8][12];
    int r0 = blockIdx.x * 4;
    int tid = threadIdx.x, warp = tid >> 5, lane = tid & 31;
    float acc[4][3];
#pragma unroll
    for (int rr = 0; rr < 4; rr++)
#pragma unroll
        for (int j = 0; j < 3; j++) acc[rr][j] = 0.f;

    for (int it = 0; it < NN / 4 / 256; it++) {
        int idx = tid + it * 256;            // float4 index along columns
        const float4* wcp = reinterpret_cast<const float4*>(g_Wc + (size_t)idx * 64);
        float4 wc[16];
#pragma unroll
        for (int q = 0; q < 16; q++) wc[q] = wcp[q];
#pragma unroll
        for (int rr = 0; rr < 4; rr++) {
            float4 v0 = reinterpret_cast<const float4*>(a0 + (size_t)(r0 + rr) * NN)[idx];
            float4 v1 = reinterpret_cast<const float4*>(a1 + (size_t)(r0 + rr) * NN)[idx];
            float4 v2 = reinterpret_cast<const float4*>(a2 + (size_t)(r0 + rr) * NN)[idx];
            const float av[3][4] = {{v0.x, v0.y, v0.z, v0.w},
                                    {v1.x, v1.y, v1.z, v1.w},
                                    {v2.x, v2.y, v2.z, v2.w}};
#pragma unroll
            for (int cc = 0; cc < 4; cc++)
#pragma unroll
                for (int i = 0; i < 3; i++) {
                    float4 w = wc[cc * 4 + i];
                    float a = av[i][cc];
                    acc[rr][0] = fmaf(a, w.x, acc[rr][0]);
                    acc[rr][1] = fmaf(a, w.y, acc[rr][1]);
                    acc[rr][2] = fmaf(a, w.z, acc[rr][2]);
                }
        }
    }
#pragma unroll
    for (int rr = 0; rr < 4; rr++)
#pragma unroll
        for (int j = 0; j < 3; j++) {
            float v = acc[rr][j];
#pragma unroll
            for (int off = 16; off; off >>= 1) v += __shfl_xor_sync(0xffffffffu, v, off);
            if (lane == 0) red[warp][rr * 3 + j] = v;
        }
    __syncthreads();
    if (tid == 0) {
#pragma unroll
        for (int rr = 0; rr < 4; rr++) {
            float z0 = g_bc[0], z1 = g_bc[1], z2 = g_bc[2];
#pragma unroll
            for (int w = 0; w < 8; w++) {
                z0 += red[w][rr * 3 + 0]; z1 += red[w][rr * 3 + 1]; z2 += red[w][rr * 3 + 2];
            }
            float m = fmaxf(z0, fmaxf(z1, z2));
            float e0 = __expf(z0 - m), e1 = __expf(z1 - m), e2 = __expf(z2 - m);
            float inv = 1.f / (e0 + e1 + e2);
            int row = r0 + rr;
            g_nz[row * 3 + 0] = e0 * inv; g_nz[row * 3 + 1] = e1 * inv; g_nz[row * 3 + 2] = e2 * inv;
            if (out_nz) {
                out_nz[row * 3 + 0] = e0 * inv; out_nz[row * 3 + 1] = e1 * inv;
                out_nz[row * 3 + 2] = e2 * inv;
            }
        }
    }
}

// ---------------- adj[r,c] = sum_i nz[c,i] * adj_i[r,c] ---------------------
__global__ __launch_bounds__(256)
void combine_adj_kernel(const float* __restrict__ a0,
                        const float* __restrict__ a1,
                        const float* __restrict__ a2)
{
    size_t idx = (size_t)blockIdx.x * 256 + threadIdx.x;   // float4 index
    int c = (int)(idx % (NN / 4)) * 4;
    float4 v0 = ((const float4*)a0)[idx];
    float4 v1 = ((const float4*)a1)[idx];
    float4 v2 = ((const float4*)a2)[idx];
    float4 r;
    r.x = g_nz[(c + 0) * 3] * v0.x + g_nz[(c + 0) * 3 + 1] * v1.x + g_nz[(c + 0) * 3 + 2] * v2.x;
    r.y = g_nz[(c + 1) * 3] * v0.y + g_nz[(c + 1) * 3 + 1] * v1.y + g_nz[(c + 1) * 3 + 2] * v2.y;
    r.z = g_nz[(c + 2) * 3] * v0.z + g_nz[(c + 2) * 3 + 1] * v1.z + g_nz[(c + 2) * 3 + 2] * v2.z;
    r.w = g_nz[(c + 3) * 3] * v0.w + g_nz[(c + 3) * 3 + 1] * v1.w + g_nz[(c + 3) * 3 + 2] * v2.w;
    ((float4*)g_adj)[idx] = r;
}

// ---------------- attention = row-softmax(adj * S), in place ----------------
// (_gcn_norm of a row-softmax is identity to ~1e-9; skipped.)
__global__ __launch_bounds__(256)
void att_softmax_kernel()
{
    __shared__ float sv[NN];
    __shared__ float red[8];
    int row = blockIdx.x, tid = threadIdx.x;
    const float* ar = g_adj + (size_t)row * NN;
    float* sr = g_S + (size_t)row * NN;

    float m = -3.4e38f;
    for (int j = tid; j < NN; j += 256) {
        float v = ar[j] * sr[j];
        sv[j] = v;
        m = fmaxf(m, v);
    }
#pragma unroll
    for (int off = 16; off; off >>= 1) m = fmaxf(m, __shfl_xor_sync(0xffffffffu, m, off));
    if ((tid & 31) == 0) red[tid >> 5] = m;
    __syncthreads();
    float M = -3.4e38f;
#pragma unroll
    for (int i = 0; i < 8; i++) M = fmaxf(M, red[i]);
    __syncthreads();

    float s = 0.f;
    for (int j = tid; j < NN; j += 256) {
        float e = __expf(sv[j] - M);
        sv[j] = e;
        s += e;
    }
#pragma unroll
    for (int off = 16; off; off >>= 1) s += __shfl_xor_sync(0xffffffffu, s, off);
    if ((tid & 31) == 0) red[tid >> 5] = s;
    __syncthreads();
    float S = 0.f;
#pragma unroll
    for (int i = 0; i < 8; i++) S += red[i];
    float inv = 1.f / S;

    for (int j = tid; j < NN; j += 256) sr[j] = sv[j] * inv;
}

// ---------------- XW2 = X_tilde @ W2  (N=8) ---------------------------------
__global__ __launch_bounds__(256)
void xw2_kernel(const float* __restrict__ W2)
{
    __shared__ float sW[NHID][9];
    int tid = threadIdx.x;
    for (int i = tid; i < NHID * NCLASS; i += 256) sW[i / 8][i % 8] = W2[i];
    __syncthreads();
    int warp = tid >> 5, lane = tid & 31;
    int row = blockIdx.x * 8 + warp;
    const float* xr = g_Xt + (size_t)row * NHID;
    float acc[8] = {0, 0, 0, 0, 0, 0, 0, 0};
#pragma unroll
    for (int it = 0; it < NHID / 32; it++) {
        int k = it * 32 + lane;
        float xv = xr[k];
#pragma unroll
        for (int j = 0; j < 8; j++) acc[j] = fmaf(xv, sW[k][j], acc[j]);
    }
#pragma unroll
    for (int j = 0; j < 8; j++)
#pragma unroll
        for (int off = 16; off; off >>= 1)
            acc[j] += __shfl_xor_sync(0xffffffffu, acc[j], off);
    if (lane == 0) {
#pragma unroll
        for (int j = 0; j < 8; j++) g_XW2[(size_t)row * 8 + j] = acc[j];
    }
}

// ---------------- z = adj @ XW2 + b2 ; softmax rows -> out ------------------
__global__ __launch_bounds__(256)
void z_out_kernel(const float* __restrict__ b2, float* __restrict__ out)
{
    __shared__ float sW[512][9];
    int tid = threadIdx.x, warp = tid >> 5, lane = tid & 31;
    int row = blockIdx.x * 8 + warp;
    const float* ar = g_adj + (size_t)row * NN;
    float acc[8] = {0, 0, 0, 0, 0, 0, 0, 0};
    for (int c0 = 0; c0 < NN; c0 += 512) {
        __syncthreads();
        for (int i = tid; i < 512 * 8; i += 256) sW[i / 8][i % 8] = g_XW2[(size_t)(c0) * 8 + i];
        __syncthreads();
#pragma unroll
        for (int it = 0; it < 16; it++) {
            int k = it * 32 + lane;
            float a = ar[c0 + k];
#pragma unroll
            for (int j = 0; j < 8; j++) acc[j] = fmaf(a, sW[k][j], acc[j]);
        }
    }
#pragma unroll
    for (int j = 0; j < 8; j++)
#pragma unroll
        for (int off = 16; off; off >>= 1)
            acc[j] += __shfl_xor_sync(0xffffffffu, acc[j], off);
    if (lane == 0) {
        float z[8]; float m = -3.4e38f;
#pragma unroll
        for (int j = 0; j < 8; j++) { z[j] = acc[j] + b2[j]; m = fmaxf(m, z[j]); }
        float s = 0.f;
#pragma unroll
        for (int j = 0; j < 8; j++) { z[j] = __expf(z[j] - m); s += z[j]; }
        float inv = 1.f / s;
#pragma unroll
        for (int j = 0; j < 8; j++) out[(size_t)row * 8 + j] = z[j] * inv;
    }
}

// ---------------- launch ----------------------------------------------------
extern "C" void kernel_launch(void* const* d_in, const int* in_sizes, int n_in,
                              void* d_out, int out_size)
{
    const float* adj0 = (const float*)d_in[0];
    const float* adj1 = (const float*)d_in[1];
    const float* adj2 = (const float*)d_in[2];
    const float* feat = (const float*)d_in[3];
    const float* Wa1  = (const float*)d_in[4];
    const float* ba1  = (const float*)d_in[5];
    const float* Wa2  = (const float*)d_in[6];
    const float* ba2  = (const float*)d_in[7];
    const float* Wa3  = (const float*)d_in[8];
    const float* ba3  = (const float*)d_in[9];
    const float* Wagg = (const float*)d_in[10];
    const float* bagg = (const float*)d_in[11];
    const float* W1   = (const float*)d_in[12];
    const float* b1   = (const float*)d_in[13];
    const float* Wq   = (const float*)d_in[14];
    const float* bq   = (const float*)d_in[15];
    const float* Wk   = (const float*)d_in[16];
    const float* bk   = (const float*)d_in[17];
    const float* Wv   = (const float*)d_in[18];
    const float* bv   = (const float*)d_in[19];
    const float* W2   = (const float*)d_in[20];
    const float* b2   = (const float*)d_in[21];
    float* out = (float*)d_out;

    float *adjC, *S, *XW1, *XW1T, *x, *Q, *Kh, *V, *VT, *Xt;
    float *W1T, *WqT, *WkT, *WvT;
    cudaGetSymbolAddress((void**)&adjC, g_adj);
    cudaGetSymbolAddress((void**)&S,    g_S);
    cudaGetSymbolAddress((void**)&XW1,  g_XW1);
    cudaGetSymbolAddress((void**)&XW1T, g_XW1T);
    cudaGetSymbolAddress((void**)&x,    g_x);
    cudaGetSymbolAddress((void**)&Q,    g_Q);
    cudaGetSymbolAddress((void**)&Kh,   g_Kh);
    cudaGetSymbolAddress((void**)&V,    g_V);
    cudaGetSymbolAddress((void**)&VT,   g_VT);
    cudaGetSymbolAddress((void**)&Xt,   g_Xt);
    cudaGetSymbolAddress((void**)&W1T,  g_W1T);
    cudaGetSymbolAddress((void**)&WqT,  g_WqT);
    cudaGetSymbolAddress((void**)&WkT,  g_WkT);
    cudaGetSymbolAddress((void**)&WvT,  g_WvT);

    cudaFuncSetAttribute(mma_gemm_kernel<0>, cudaFuncAttributeMaxDynamicSharedMemorySize, MMA_SMEM);
    cudaFuncSetAttribute(mma_gemm_kernel<1>, cudaFuncAttributeMaxDynamicSharedMemorySize, MMA_SMEM);
    cudaFuncSetAttribute(mma_gemm_kernel<2>, cudaFuncAttributeMaxDynamicSharedMemorySize, MMA_SMEM);
    cudaFuncSetAttribute(mma_gemm_kernel<3>, cudaFuncAttributeMaxDynamicSharedMemorySize, MMA_SMEM);

    dim3 tb(32, 8);
    // small weight transposes ([K,N] -> [N,K] for the MMA B operand)
    transpose_kernel<<<dim3(NHID / 32, NFEAT / 32), tb>>>(W1, W1T, NFEAT, NHID);
    transpose_kernel<<<dim3(NHID / 32, NHID / 32), tb>>>(Wq, WqT, NHID, NHID);
    transpose_kernel<<<dim3(NHID / 32, NHID / 32), tb>>>(Wk, WkT, NHID, NHID);
    transpose_kernel<<<dim3(NHID / 32, NHID / 32), tb>>>(Wv, WvT, NHID, NHID);

    // 1) Wc = Wa_i @ Wagg_block_i  (tiny; replaces the 87-GF z-GEMM)
    wc_kernel<<<(3 * NN + 255) / 256, 256>>>(Wa1, Wa2, Wa3, Wagg, ba1, ba2, ba3, bagg);

    // 2) z4 = Σ adj_i @ Wc_i + bc ; nz = softmax3 (bandwidth pass, fp32-exact)
    float* out_nz = (out_size >= NN * (NCLASS + 3)) ? out + (size_t)NN * NCLASS : nullptr;
    z4nz_kernel<<<NN / 4, 256>>>(adj0, adj1, adj2, out_nz);

    // 3) adj = column-weighted combination
    combine_adj_kernel<<<(NN / 4) * (NN / 256), 256>>>(adj0, adj1, adj2);

    // 4) XW1 = features @ W1
    mma_gemm_kernel<0><<<dim3(NN / 128, NHID / 128, 1), 256, MMA_SMEM>>>(
        feat, feat, feat, W1T, W1T, W1T, nullptr, nullptr, nullptr,
        XW1, XW1, XW1, NHID, NFEAT);
    transpose_kernel<<<dim3(NHID / 32, NN / 32), tb>>>(XW1, XW1T, NN, NHID);

    // 5) x = relu(adj @ XW1 + b1)
    mma_gemm_kernel<3><<<dim3(NN / 128, NHID / 128, 1), 256, MMA_SMEM>>>(
        adjC, adjC, adjC, XW1T, XW1T, XW1T, b1, b1, b1,
        x, x, x, NHID, NN);

    // 6) Q, K, V fused over blockIdx.z
    mma_gemm_kernel<1><<<dim3(NN / 128, NHID / 128, 3), 256, MMA_SMEM>>>(
        x, x, x, WqT, WkT, WvT, bq, bk, bv,
        Q, Kh, V, NHID, NHID);
    transpose_kernel<<<dim3(NHID / 32, NN / 32), tb>>>(V, VT, NN, NHID);

    // 7) S = Q @ K^T   (K_h is already [N,K] for the B operand)
    mma_gemm_kernel<0><<<dim3(NN / 128, NN / 128, 1), 256, MMA_SMEM>>>(
        Q, Q, Q, Kh, Kh, Kh, nullptr, nullptr, nullptr,
        S, S, S, NN, NHID);

    // 8) attention = row-softmax(adj * S)   (gcn_norm == identity, skipped)
    att_softmax_kernel<<<NN, 256>>>();

    // 9) X_tilde = relu(attention @ V)
    mma_gemm_kernel<2><<<dim3(NN / 128, NHID / 128, 1), 256, MMA_SMEM>>>(
        S, S, S, VT, VT, VT, nullptr, nullptr, nullptr,
        Xt, Xt, Xt, NHID, NN);

    // 10) XW2 = X_tilde @ W2
    xw2_kernel<<<NN / 8, 256>>>(W2);

    // 11) z = adj @ XW2 + b2 ; row softmax -> out[0 : N*8)
    z_out_kernel<<<NN / 8, 256>>>(b2, out);
}